// round 14
// baseline (speedup 1.0000x reference)
#include <cuda_runtime.h>
#include <math.h>

#define C 128
#define CV 32            // C/4 float4 per row
#define HID 8
#define NB 16

#define RED_BLOCKS 592

// Scratch (no allocations allowed). Zero-initialized at load; mlp_kernel
// re-zeroes g_sums/g_counts after consuming them -> every call starts clean.
__device__ float g_sums[NB][C];
__device__ float g_counts[NB];
__device__ float g_gate[NB][C];

// ---------------------------------------------------------------------------
// 1) segment sum — branchless chunked form, unroll SIXTEEN (was 8).
//    __launch_bounds__(256,3) grants ~85 regs so 16 float4 rows stay in
//    flight per warp: 24 warps/SM x 8KB = 192KB in-flight/SM (+50% vs R12).
//    Single-variable test: per-warp load depth vs the 4.7 TB/s plateau.
// ---------------------------------------------------------------------------
__device__ __forceinline__ int lower_bound_idx(const int* __restrict__ bidx,
                                               int lo, int hi, int val) {
    while (lo < hi) {
        int mid = (lo + hi) >> 1;
        if (bidx[mid] < val) lo = mid + 1; else hi = mid;
    }
    return lo;
}

__global__ __launch_bounds__(256, 3) void reduce_kernel(
    const float4* __restrict__ x, const int* __restrict__ bidx,
    int n, int rows_per_block)
{
    int row0 = blockIdx.x * rows_per_block;
    int row1 = row0 + rows_per_block;
    if (row1 > n) row1 = n;
    if (row0 >= row1) return;

    int warp = threadIdx.x >> 5;
    int lane = threadIdx.x & 31;

    int b_first = bidx[row0];
    int b_last  = bidx[row1 - 1];

    int seg_start = row0;
    for (int b = b_first; b <= b_last; b++) {
        int seg_end = (b == b_last) ? row1
                    : lower_bound_idx(bidx, seg_start, row1, b + 1);

        float4 accA = make_float4(0.f, 0.f, 0.f, 0.f);
        float4 accB = make_float4(0.f, 0.f, 0.f, 0.f);

        int r = seg_start + warp;
        // main: 16 rows in flight per warp (128-row stride per iteration)
        for (; r + 120 < seg_end; r += 128) {
            float4 v0  = x[(size_t)(r)       * CV + lane];
            float4 v1  = x[(size_t)(r + 8)   * CV + lane];
            float4 v2  = x[(size_t)(r + 16)  * CV + lane];
            float4 v3  = x[(size_t)(r + 24)  * CV + lane];
            float4 v4  = x[(size_t)(r + 32)  * CV + lane];
            float4 v5  = x[(size_t)(r + 40)  * CV + lane];
            float4 v6  = x[(size_t)(r + 48)  * CV + lane];
            float4 v7  = x[(size_t)(r + 56)  * CV + lane];
            float4 v8  = x[(size_t)(r + 64)  * CV + lane];
            float4 v9  = x[(size_t)(r + 72)  * CV + lane];
            float4 v10 = x[(size_t)(r + 80)  * CV + lane];
            float4 v11 = x[(size_t)(r + 88)  * CV + lane];
            float4 v12 = x[(size_t)(r + 96)  * CV + lane];
            float4 v13 = x[(size_t)(r + 104) * CV + lane];
            float4 v14 = x[(size_t)(r + 112) * CV + lane];
            float4 v15 = x[(size_t)(r + 120) * CV + lane];
            accA.x += v0.x;  accA.y += v0.y;  accA.z += v0.z;  accA.w += v0.w;
            accB.x += v1.x;  accB.y += v1.y;  accB.z += v1.z;  accB.w += v1.w;
            accA.x += v2.x;  accA.y += v2.y;  accA.z += v2.z;  accA.w += v2.w;
            accB.x += v3.x;  accB.y += v3.y;  accB.z += v3.z;  accB.w += v3.w;
            accA.x += v4.x;  accA.y += v4.y;  accA.z += v4.z;  accA.w += v4.w;
            accB.x += v5.x;  accB.y += v5.y;  accB.z += v5.z;  accB.w += v5.w;
            accA.x += v6.x;  accA.y += v6.y;  accA.z += v6.z;  accA.w += v6.w;
            accB.x += v7.x;  accB.y += v7.y;  accB.z += v7.z;  accB.w += v7.w;
            accA.x += v8.x;  accA.y += v8.y;  accA.z += v8.z;  accA.w += v8.w;
            accB.x += v9.x;  accB.y += v9.y;  accB.z += v9.z;  accB.w += v9.w;
            accA.x += v10.x; accA.y += v10.y; accA.z += v10.z; accA.w += v10.w;
            accB.x += v11.x; accB.y += v11.y; accB.z += v11.z; accB.w += v11.w;
            accA.x += v12.x; accA.y += v12.y; accA.z += v12.z; accA.w += v12.w;
            accB.x += v13.x; accB.y += v13.y; accB.z += v13.z; accB.w += v13.w;
            accA.x += v14.x; accA.y += v14.y; accA.z += v14.z; accA.w += v14.w;
            accB.x += v15.x; accB.y += v15.y; accB.z += v15.z; accB.w += v15.w;
        }
        // mid: 4 rows in flight (32-row stride) to shrink the tail
        for (; r + 24 < seg_end; r += 32) {
            float4 v0 = x[(size_t)(r)      * CV + lane];
            float4 v1 = x[(size_t)(r + 8)  * CV + lane];
            float4 v2 = x[(size_t)(r + 16) * CV + lane];
            float4 v3 = x[(size_t)(r + 24) * CV + lane];
            accA.x += v0.x; accA.y += v0.y; accA.z += v0.z; accA.w += v0.w;
            accB.x += v1.x; accB.y += v1.y; accB.z += v1.z; accB.w += v1.w;
            accA.x += v2.x; accA.y += v2.y; accA.z += v2.z; accA.w += v2.w;
            accB.x += v3.x; accB.y += v3.y; accB.z += v3.z; accB.w += v3.w;
        }
        for (; r < seg_end; r += 8) {
            float4 v = x[(size_t)r * CV + lane];
            accA.x += v.x; accA.y += v.y; accA.z += v.z; accA.w += v.w;
        }

        int seg_len = seg_end - seg_start;
        if (seg_len > 0) {
            float* dst = &g_sums[b][lane * 4];
            atomicAdd(dst + 0, accA.x + accB.x);
            atomicAdd(dst + 1, accA.y + accB.y);
            atomicAdd(dst + 2, accA.z + accB.z);
            atomicAdd(dst + 3, accA.w + accB.w);
            if (lane == 0 && warp == 0)
                atomicAdd(&g_counts[b], (float)seg_len);
        }
        seg_start = seg_end;
    }
}

// ---------------------------------------------------------------------------
// 2) tiny MLP (R9 fast version): 256 threads, weights cooperatively
//    preloaded vectorized. Re-zeroes accumulators for the next invocation.
// ---------------------------------------------------------------------------
__global__ __launch_bounds__(256) void mlp_kernel(
    const float* __restrict__ W1, const float* __restrict__ b1,
    const float* __restrict__ W2, const float* __restrict__ b2)
{
    __shared__ float sW1[C * HID];
    __shared__ float sW2[HID * C];
    __shared__ float s_b1[HID];
    __shared__ float s_b2[C];
    __shared__ float s_mean[NB][C];
    __shared__ float s_h[NB][HID];

    int t = threadIdx.x;  // 0..255

    for (int i = t; i < (C * HID) / 4; i += 256) {
        ((float4*)sW1)[i] = ((const float4*)W1)[i];
        ((float4*)sW2)[i] = ((const float4*)W2)[i];
    }
    if (t < HID) s_b1[t] = b1[t];
    if (t < C)   s_b2[t] = b2[t];
    for (int i = t; i < NB * C; i += 256) {
        int b = i / C;
        float cn = fmaxf(g_counts[b], 1.0f);
        ((float*)s_mean)[i] = ((const float*)g_sums)[i] / cn;
    }
    __syncthreads();

    // reset accumulators for the next invocation
    for (int i = t; i < NB * C; i += 256) ((float*)g_sums)[i] = 0.0f;
    if (t < NB) g_counts[t] = 0.0f;

    if (t < NB * HID) {                // 128 outputs: h[b][j]
        int b = t / HID, j = t % HID;
        float acc = s_b1[j];
        #pragma unroll 8
        for (int c = 0; c < C; c++) acc += s_mean[b][c] * sW1[c * HID + j];
        s_h[b][j] = fmaxf(acc, 0.0f);
    }
    __syncthreads();

    if (t < C) {                       // gate column c = t
        int c = t;
        float w2c[HID];
        #pragma unroll
        for (int j = 0; j < HID; j++) w2c[j] = sW2[j * C + c];
        float bias = s_b2[c];
        for (int b = 0; b < NB; b++) {
            float acc = bias;
            #pragma unroll
            for (int j = 0; j < HID; j++) acc += s_h[b][j] * w2c[j];
            g_gate[b][c] = 1.0f / (1.0f + expf(-acc));
        }
    }
}

// ---------------------------------------------------------------------------
// 3) apply gate — R13 measured-best: same 592-chunk mapping as reduce,
//    DESCENDING walk (chunk tails still L2-resident from reduce), plain
//    loads/stores, unroll-4 front-batched.
// ---------------------------------------------------------------------------
__global__ __launch_bounds__(256) void apply_kernel(
    const float4* __restrict__ x, const int* __restrict__ bidx,
    float4* __restrict__ out, int n, int rows_per_block)
{
    __shared__ float4 s_gate[NB][CV];  // 8 KB
    for (int i = threadIdx.x; i < NB * CV; i += blockDim.x)
        ((float4*)s_gate)[i] = ((const float4*)g_gate)[i];
    __syncthreads();

    int row0 = blockIdx.x * rows_per_block;
    int row1 = row0 + rows_per_block;
    if (row1 > n) row1 = n;
    if (row0 >= row1) return;

    int warp = threadIdx.x >> 5;
    int lane = threadIdx.x & 31;

    int r = row1 - 1 - warp;
    for (; r - 24 >= row0; r -= 32) {
        int r1 = r - 8, r2 = r - 16, r3 = r - 24;
        int b0 = bidx[r];
        int b1 = bidx[r1];
        int b2 = bidx[r2];
        int b3 = bidx[r3];
        float4 v0 = x[(size_t)r  * CV + lane];
        float4 v1 = x[(size_t)r1 * CV + lane];
        float4 v2 = x[(size_t)r2 * CV + lane];
        float4 v3 = x[(size_t)r3 * CV + lane];
        float4 g0 = s_gate[b0][lane];
        float4 g1 = s_gate[b1][lane];
        float4 g2 = s_gate[b2][lane];
        float4 g3 = s_gate[b3][lane];
        v0.x *= g0.x; v0.y *= g0.y; v0.z *= g0.z; v0.w *= g0.w;
        v1.x *= g1.x; v1.y *= g1.y; v1.z *= g1.z; v1.w *= g1.w;
        v2.x *= g2.x; v2.y *= g2.y; v2.z *= g2.z; v2.w *= g2.w;
        v3.x *= g3.x; v3.y *= g3.y; v3.z *= g3.z; v3.w *= g3.w;
        out[(size_t)r  * CV + lane] = v0;
        out[(size_t)r1 * CV + lane] = v1;
        out[(size_t)r2 * CV + lane] = v2;
        out[(size_t)r3 * CV + lane] = v3;
    }
    for (; r >= row0; r -= 8) {
        int b = bidx[r];
        float4 v = x[(size_t)r * CV + lane];
        float4 g = s_gate[b][lane];
        v.x *= g.x; v.y *= g.y; v.z *= g.z; v.w *= g.w;
        out[(size_t)r * CV + lane] = v;
    }
}

// ---------------------------------------------------------------------------
extern "C" void kernel_launch(void* const* d_in, const int* in_sizes, int n_in,
                              void* d_out, int out_size)
{
    const float* x    = (const float*)d_in[0];
    const int*   bidx = (const int*)d_in[1];
    const float* W1   = (const float*)d_in[2];
    const float* b1   = (const float*)d_in[3];
    const float* W2   = (const float*)d_in[4];
    const float* b2   = (const float*)d_in[5];
    float* out = (float*)d_out;

    int n = in_sizes[1];  // number of rows (batch_idx has N entries)
    int rows_per_block = (n + RED_BLOCKS - 1) / RED_BLOCKS;

    reduce_kernel<<<RED_BLOCKS, 256>>>((const float4*)x, bidx, n, rows_per_block);
    mlp_kernel<<<1, 256>>>(W1, b1, W2, b2);
    apply_kernel<<<RED_BLOCKS, 256>>>((const float4*)x, bidx, (float4*)out, n,
                                      rows_per_block);
}

// round 15
// speedup vs baseline: 1.0588x; 1.0588x over previous
#include <cuda_runtime.h>
#include <math.h>

#define C 128
#define CV 32            // C/4 float4 per row
#define HID 8
#define NB 16

#define RED_BLOCKS 592   // 4 blocks/SM single wave at 38 regs

// Scratch (no allocations allowed). Zero-initialized at load; apply_kernel's
// read-ticket path re-zeroes g_sums/g_counts and resets g_done after ALL
// blocks have consumed them -> every call starts from zeros. Deterministic.
__device__ float g_sums[NB][C];
__device__ float g_counts[NB];
__device__ unsigned int g_done;

// ---------------------------------------------------------------------------
// 1) segment sum — R12/R13 measured-best form (55.4us, regs=38). Chunked,
//    ascending, branchless per-segment streaming (unroll 8, two accums).
// ---------------------------------------------------------------------------
__device__ __forceinline__ int lower_bound_idx(const int* __restrict__ bidx,
                                               int lo, int hi, int val) {
    while (lo < hi) {
        int mid = (lo + hi) >> 1;
        if (bidx[mid] < val) lo = mid + 1; else hi = mid;
    }
    return lo;
}

__global__ __launch_bounds__(256) void reduce_kernel(
    const float4* __restrict__ x, const int* __restrict__ bidx,
    int n, int rows_per_block)
{
    int row0 = blockIdx.x * rows_per_block;
    int row1 = row0 + rows_per_block;
    if (row1 > n) row1 = n;
    if (row0 >= row1) return;

    int warp = threadIdx.x >> 5;
    int lane = threadIdx.x & 31;

    int b_first = bidx[row0];
    int b_last  = bidx[row1 - 1];

    int seg_start = row0;
    for (int b = b_first; b <= b_last; b++) {
        int seg_end = (b == b_last) ? row1
                    : lower_bound_idx(bidx, seg_start, row1, b + 1);

        float4 accA = make_float4(0.f, 0.f, 0.f, 0.f);
        float4 accB = make_float4(0.f, 0.f, 0.f, 0.f);

        int r = seg_start + warp;
        for (; r + 56 < seg_end; r += 64) {
            float4 v0 = x[(size_t)(r)      * CV + lane];
            float4 v1 = x[(size_t)(r + 8)  * CV + lane];
            float4 v2 = x[(size_t)(r + 16) * CV + lane];
            float4 v3 = x[(size_t)(r + 24) * CV + lane];
            float4 v4 = x[(size_t)(r + 32) * CV + lane];
            float4 v5 = x[(size_t)(r + 40) * CV + lane];
            float4 v6 = x[(size_t)(r + 48) * CV + lane];
            float4 v7 = x[(size_t)(r + 56) * CV + lane];
            accA.x += v0.x; accA.y += v0.y; accA.z += v0.z; accA.w += v0.w;
            accB.x += v1.x; accB.y += v1.y; accB.z += v1.z; accB.w += v1.w;
            accA.x += v2.x; accA.y += v2.y; accA.z += v2.z; accA.w += v2.w;
            accB.x += v3.x; accB.y += v3.y; accB.z += v3.z; accB.w += v3.w;
            accA.x += v4.x; accA.y += v4.y; accA.z += v4.z; accA.w += v4.w;
            accB.x += v5.x; accB.y += v5.y; accB.z += v5.z; accB.w += v5.w;
            accA.x += v6.x; accA.y += v6.y; accA.z += v6.z; accA.w += v6.w;
            accB.x += v7.x; accB.y += v7.y; accB.z += v7.z; accB.w += v7.w;
        }
        for (; r < seg_end; r += 8) {
            float4 v = x[(size_t)r * CV + lane];
            accA.x += v.x; accA.y += v.y; accA.z += v.z; accA.w += v.w;
        }

        int seg_len = seg_end - seg_start;
        if (seg_len > 0) {
            float* dst = &g_sums[b][lane * 4];
            atomicAdd(dst + 0, accA.x + accB.x);
            atomicAdd(dst + 1, accA.y + accB.y);
            atomicAdd(dst + 2, accA.z + accB.z);
            atomicAdd(dst + 3, accA.w + accB.w);
            if (lane == 0 && warp == 0)
                atomicAdd(&g_counts[b], (float)seg_len);
        }
        seg_start = seg_end;
    }
}

// ---------------------------------------------------------------------------
// 2) apply gate with FUSED MLP head (no separate mlp launch):
//    Every block redundantly computes the tiny SE MLP (weights cooperatively
//    preloaded -> one latency batch; g_sums/g_counts are hot L2 after reduce).
//    Read-ticket cleanup: each block bumps g_done AFTER reading g_sums; the
//    last block (all readers provably done) zeroes g_sums/g_counts and
//    resets the ticket. Then: R13 measured-best streaming — same 592-chunk
//    mapping as reduce, DESCENDING walk (chunk tails L2-resident), plain
//    loads/stores, unroll-4 front-batched.
// ---------------------------------------------------------------------------
__global__ __launch_bounds__(256) void apply_kernel(
    const float4* __restrict__ x, const int* __restrict__ bidx,
    const float* __restrict__ W1, const float* __restrict__ b1,
    const float* __restrict__ W2, const float* __restrict__ b2,
    float4* __restrict__ out, int n, int rows_per_block)
{
    __shared__ float sW1[C * HID];      // 4 KB
    __shared__ float sW2[HID * C];      // 4 KB
    __shared__ float s_b1[HID];
    __shared__ float s_b2[C];
    __shared__ float s_mean[NB][C];     // 8 KB
    __shared__ float s_h[NB][HID];
    __shared__ float4 s_gate[NB][CV];   // 8 KB
    __shared__ unsigned int s_last;

    int t = threadIdx.x;  // 0..255

    // --- batched preloads (independent -> single latency exposure) ---
    for (int i = t; i < (C * HID) / 4; i += 256) {
        ((float4*)sW1)[i] = ((const float4*)W1)[i];
        ((float4*)sW2)[i] = ((const float4*)W2)[i];
    }
    if (t < HID) s_b1[t] = b1[t];
    if (t < C)   s_b2[t] = b2[t];
    for (int i = t; i < NB * C; i += 256) {
        int b = i / C;
        float cn = fmaxf(g_counts[b], 1.0f);
        ((float*)s_mean)[i] = ((const float*)g_sums)[i] / cn;
    }
    __syncthreads();          // all reads of g_sums/g_counts complete

    // --- read-ticket: last block to finish reading zeroes the accumulators ---
    __threadfence();
    if (t == 0) {
        unsigned int old = atomicAdd(&g_done, 1u);
        s_last = (old == (unsigned int)gridDim.x - 1u) ? 1u : 0u;
    }
    __syncthreads();
    if (s_last) {
        for (int i = t; i < NB * C; i += 256) ((float*)g_sums)[i] = 0.0f;
        if (t < NB) g_counts[t] = 0.0f;
        if (t == 0) g_done = 0u;
    }

    // --- tiny MLP (redundant per block, ~1us) ---
    if (t < NB * HID) {                 // 128 outputs: h[b][j]
        int b = t / HID, j = t % HID;
        float acc = s_b1[j];
        #pragma unroll 8
        for (int c = 0; c < C; c++) acc += s_mean[b][c] * sW1[c * HID + j];
        s_h[b][j] = fmaxf(acc, 0.0f);
    }
    __syncthreads();

    if (t < C) {                        // gate column c = t
        int c = t;
        float w2c[HID];
        #pragma unroll
        for (int j = 0; j < HID; j++) w2c[j] = sW2[j * C + c];
        float bias = s_b2[c];
        for (int b = 0; b < NB; b++) {
            float acc = bias;
            #pragma unroll
            for (int j = 0; j < HID; j++) acc += s_h[b][j] * w2c[j];
            ((float*)s_gate)[b * C + c] = 1.0f / (1.0f + expf(-acc));
        }
    }
    __syncthreads();

    // --- streaming phase (R13 measured-best) ---
    int row0 = blockIdx.x * rows_per_block;
    int row1 = row0 + rows_per_block;
    if (row1 > n) row1 = n;
    if (row0 >= row1) return;

    int warp = t >> 5;
    int lane = t & 31;

    int r = row1 - 1 - warp;
    for (; r - 24 >= row0; r -= 32) {
        int r1 = r - 8, r2 = r - 16, r3 = r - 24;
        int b0 = bidx[r];
        int b1i = bidx[r1];
        int b2i = bidx[r2];
        int b3 = bidx[r3];
        float4 v0 = x[(size_t)r  * CV + lane];
        float4 v1 = x[(size_t)r1 * CV + lane];
        float4 v2 = x[(size_t)r2 * CV + lane];
        float4 v3 = x[(size_t)r3 * CV + lane];
        float4 g0 = s_gate[b0][lane];
        float4 g1 = s_gate[b1i][lane];
        float4 g2 = s_gate[b2i][lane];
        float4 g3 = s_gate[b3][lane];
        v0.x *= g0.x; v0.y *= g0.y; v0.z *= g0.z; v0.w *= g0.w;
        v1.x *= g1.x; v1.y *= g1.y; v1.z *= g1.z; v1.w *= g1.w;
        v2.x *= g2.x; v2.y *= g2.y; v2.z *= g2.z; v2.w *= g2.w;
        v3.x *= g3.x; v3.y *= g3.y; v3.z *= g3.z; v3.w *= g3.w;
        out[(size_t)r  * CV + lane] = v0;
        out[(size_t)r1 * CV + lane] = v1;
        out[(size_t)r2 * CV + lane] = v2;
        out[(size_t)r3 * CV + lane] = v3;
    }
    for (; r >= row0; r -= 8) {
        int b = bidx[r];
        float4 v = x[(size_t)r * CV + lane];
        float4 g = s_gate[b][lane];
        v.x *= g.x; v.y *= g.y; v.z *= g.z; v.w *= g.w;
        out[(size_t)r * CV + lane] = v;
    }
}

// ---------------------------------------------------------------------------
extern "C" void kernel_launch(void* const* d_in, const int* in_sizes, int n_in,
                              void* d_out, int out_size)
{
    const float* x    = (const float*)d_in[0];
    const int*   bidx = (const int*)d_in[1];
    const float* W1   = (const float*)d_in[2];
    const float* b1   = (const float*)d_in[3];
    const float* W2   = (const float*)d_in[4];
    const float* b2   = (const float*)d_in[5];
    float* out = (float*)d_out;

    int n = in_sizes[1];  // number of rows (batch_idx has N entries)
    int rows_per_block = (n + RED_BLOCKS - 1) / RED_BLOCKS;

    reduce_kernel<<<RED_BLOCKS, 256>>>((const float4*)x, bidx, n, rows_per_block);
    apply_kernel<<<RED_BLOCKS, 256>>>((const float4*)x, bidx,
                                      W1, b1, W2, b2,
                                      (float4*)out, n, rows_per_block);
}

// round 16
// speedup vs baseline: 1.0891x; 1.0286x over previous
#include <cuda_runtime.h>
#include <math.h>

#define C 128
#define CV 32            // C/4 float4 per row
#define HID 8
#define NB 16

#define RED_BLOCKS 592   // 4 blocks/SM single wave (reg-capped below)

// Scratch (no allocations allowed). Zero-initialized at load; the last
// reduce block re-zeroes g_sums/g_counts/g_done after computing the gate,
// so every call (correctness, capture, replay) starts from zeros.
__device__ float g_sums[NB][C];
__device__ float g_counts[NB];
__device__ float g_gate[NB][C];
__device__ unsigned int g_done;

__device__ __forceinline__ int lower_bound_idx(const int* __restrict__ bidx,
                                               int lo, int hi, int val) {
    while (lo < hi) {
        int mid = (lo + hi) >> 1;
        if (bidx[mid] < val) lo = mid + 1; else hi = mid;
    }
    return lo;
}

// ---------------------------------------------------------------------------
// 1) segment sum (R12/R13 measured-best streaming body, 38 regs) + MLP in
//    the LAST block via done-ticket: the MLP runs during reduce's natural
//    drain on an otherwise-idle chip (producer-side fusion — unlike R15's
//    consumer-side fusion, nobody's streaming start is delayed).
//    __launch_bounds__(256,4) caps regs at 62 -> 4 blocks/SM single wave
//    guaranteed (R7's wave-split failure mode excluded by construction).
// ---------------------------------------------------------------------------
__global__ __launch_bounds__(256, 4) void reduce_mlp_kernel(
    const float4* __restrict__ x, const int* __restrict__ bidx,
    int n, int rows_per_block,
    const float* __restrict__ W1, const float* __restrict__ b1,
    const float* __restrict__ W2, const float* __restrict__ b2)
{
    int row0 = blockIdx.x * rows_per_block;
    int row1 = row0 + rows_per_block;
    if (row1 > n) row1 = n;

    int warp = threadIdx.x >> 5;
    int lane = threadIdx.x & 31;

    if (row0 < row1) {
        int b_first = bidx[row0];
        int b_last  = bidx[row1 - 1];

        int seg_start = row0;
        for (int b = b_first; b <= b_last; b++) {
            int seg_end = (b == b_last) ? row1
                        : lower_bound_idx(bidx, seg_start, row1, b + 1);

            float4 accA = make_float4(0.f, 0.f, 0.f, 0.f);
            float4 accB = make_float4(0.f, 0.f, 0.f, 0.f);

            int r = seg_start + warp;
            for (; r + 56 < seg_end; r += 64) {
                float4 v0 = x[(size_t)(r)      * CV + lane];
                float4 v1 = x[(size_t)(r + 8)  * CV + lane];
                float4 v2 = x[(size_t)(r + 16) * CV + lane];
                float4 v3 = x[(size_t)(r + 24) * CV + lane];
                float4 v4 = x[(size_t)(r + 32) * CV + lane];
                float4 v5 = x[(size_t)(r + 40) * CV + lane];
                float4 v6 = x[(size_t)(r + 48) * CV + lane];
                float4 v7 = x[(size_t)(r + 56) * CV + lane];
                accA.x += v0.x; accA.y += v0.y; accA.z += v0.z; accA.w += v0.w;
                accB.x += v1.x; accB.y += v1.y; accB.z += v1.z; accB.w += v1.w;
                accA.x += v2.x; accA.y += v2.y; accA.z += v2.z; accA.w += v2.w;
                accB.x += v3.x; accB.y += v3.y; accB.z += v3.z; accB.w += v3.w;
                accA.x += v4.x; accA.y += v4.y; accA.z += v4.z; accA.w += v4.w;
                accB.x += v5.x; accB.y += v5.y; accB.z += v5.z; accB.w += v5.w;
                accA.x += v6.x; accA.y += v6.y; accA.z += v6.z; accA.w += v6.w;
                accB.x += v7.x; accB.y += v7.y; accB.z += v7.z; accB.w += v7.w;
            }
            for (; r < seg_end; r += 8) {
                float4 v = x[(size_t)r * CV + lane];
                accA.x += v.x; accA.y += v.y; accA.z += v.z; accA.w += v.w;
            }

            int seg_len = seg_end - seg_start;
            if (seg_len > 0) {
                float* dst = &g_sums[b][lane * 4];
                atomicAdd(dst + 0, accA.x + accB.x);
                atomicAdd(dst + 1, accA.y + accB.y);
                atomicAdd(dst + 2, accA.z + accB.z);
                atomicAdd(dst + 3, accA.w + accB.w);
                if (lane == 0 && warp == 0)
                    atomicAdd(&g_counts[b], (float)seg_len);
            }
            seg_start = seg_end;
        }
    }

    // ---- last-block-done MLP tail (runs on idle chip during drain) ----
    __shared__ unsigned int s_last;
    __threadfence();                       // publish this block's atomics
    __syncthreads();
    if (threadIdx.x == 0) {
        unsigned int old = atomicAdd(&g_done, 1u);
        s_last = (old == (unsigned int)gridDim.x - 1u) ? 1u : 0u;
    }
    __syncthreads();
    if (!s_last) return;

    __threadfence();                       // acquire: see all blocks' sums

    __shared__ float s_mean[NB][C];
    __shared__ float s_h[NB][HID];
    int t = threadIdx.x;                   // 0..255

    for (int i = t; i < NB * C; i += 256) {
        int b = i / C;
        float cn = fmaxf(g_counts[b], 1.0f);
        ((float*)s_mean)[i] = ((const float*)g_sums)[i] / cn;
    }
    __syncthreads();

    // reset state for the next invocation
    for (int i = t; i < NB * C; i += 256) ((float*)g_sums)[i] = 0.0f;
    if (t < NB) g_counts[t] = 0.0f;
    if (t == 0) g_done = 0u;

    if (t < NB * HID) {                    // 128 outputs: h[b][j]
        int b = t / HID, j = t % HID;
        float acc = b1[j];
        #pragma unroll 8
        for (int c = 0; c < C; c++) acc += s_mean[b][c] * W1[c * HID + j];
        s_h[b][j] = fmaxf(acc, 0.0f);
    }
    __syncthreads();

    if (t < C) {                           // gate column c = t
        int c = t;
        float w2c[HID];
        #pragma unroll
        for (int j = 0; j < HID; j++) w2c[j] = W2[j * C + c];
        float bias = b2[c];
        for (int b = 0; b < NB; b++) {
            float acc = bias;
            #pragma unroll
            for (int j = 0; j < HID; j++) acc += s_h[b][j] * w2c[j];
            g_gate[b][c] = 1.0f / (1.0f + expf(-acc));
        }
    }
}

// ---------------------------------------------------------------------------
// 2) apply gate — EXACT R13 measured-best: same 592-chunk mapping as reduce,
//    DESCENDING walk (chunk tails L2-resident from reduce; L2 persists
//    across launches), plain loads/stores, unroll-4 front-batched.
// ---------------------------------------------------------------------------
__global__ __launch_bounds__(256) void apply_kernel(
    const float4* __restrict__ x, const int* __restrict__ bidx,
    float4* __restrict__ out, int n, int rows_per_block)
{
    __shared__ float4 s_gate[NB][CV];  // 8 KB
    for (int i = threadIdx.x; i < NB * CV; i += blockDim.x)
        ((float4*)s_gate)[i] = ((const float4*)g_gate)[i];
    __syncthreads();

    int row0 = blockIdx.x * rows_per_block;
    int row1 = row0 + rows_per_block;
    if (row1 > n) row1 = n;
    if (row0 >= row1) return;

    int warp = threadIdx.x >> 5;
    int lane = threadIdx.x & 31;

    int r = row1 - 1 - warp;
    for (; r - 24 >= row0; r -= 32) {
        int r1 = r - 8, r2 = r - 16, r3 = r - 24;
        int b0 = bidx[r];
        int b1 = bidx[r1];
        int b2 = bidx[r2];
        int b3 = bidx[r3];
        float4 v0 = x[(size_t)r  * CV + lane];
        float4 v1 = x[(size_t)r1 * CV + lane];
        float4 v2 = x[(size_t)r2 * CV + lane];
        float4 v3 = x[(size_t)r3 * CV + lane];
        float4 g0 = s_gate[b0][lane];
        float4 g1 = s_gate[b1][lane];
        float4 g2 = s_gate[b2][lane];
        float4 g3 = s_gate[b3][lane];
        v0.x *= g0.x; v0.y *= g0.y; v0.z *= g0.z; v0.w *= g0.w;
        v1.x *= g1.x; v1.y *= g1.y; v1.z *= g1.z; v1.w *= g1.w;
        v2.x *= g2.x; v2.y *= g2.y; v2.z *= g2.z; v2.w *= g2.w;
        v3.x *= g3.x; v3.y *= g3.y; v3.z *= g3.z; v3.w *= g3.w;
        out[(size_t)r  * CV + lane] = v0;
        out[(size_t)r1 * CV + lane] = v1;
        out[(size_t)r2 * CV + lane] = v2;
        out[(size_t)r3 * CV + lane] = v3;
    }
    for (; r >= row0; r -= 8) {
        int b = bidx[r];
        float4 v = x[(size_t)r * CV + lane];
        float4 g = s_gate[b][lane];
        v.x *= g.x; v.y *= g.y; v.z *= g.z; v.w *= g.w;
        out[(size_t)r * CV + lane] = v;
    }
}

// ---------------------------------------------------------------------------
extern "C" void kernel_launch(void* const* d_in, const int* in_sizes, int n_in,
                              void* d_out, int out_size)
{
    const float* x    = (const float*)d_in[0];
    const int*   bidx = (const int*)d_in[1];
    const float* W1   = (const float*)d_in[2];
    const float* b1   = (const float*)d_in[3];
    const float* W2   = (const float*)d_in[4];
    const float* b2   = (const float*)d_in[5];
    float* out = (float*)d_out;

    int n = in_sizes[1];  // number of rows (batch_idx has N entries)
    int rows_per_block = (n + RED_BLOCKS - 1) / RED_BLOCKS;

    reduce_mlp_kernel<<<RED_BLOCKS, 256>>>((const float4*)x, bidx, n,
                                           rows_per_block, W1, b1, W2, b2);
    apply_kernel<<<RED_BLOCKS, 256>>>((const float4*)x, bidx, (float4*)out, n,
                                      rows_per_block);
}